// round 8
// baseline (speedup 1.0000x reference)
#include <cuda_runtime.h>
#include <cuda_bf16.h>
#include <cstdint>
#include <math.h>

// Problem constants
#define NL  4
#define DM  1024
#define DI  2048
#define DS  16
#define DC  4
#define DTR 64
#define IN_DIM  256
#define OUT_DIM 128
#define BATCH 4096
#define XD 96          // DTR + 2*DS

// ---------------------------------------------------------------------------
// fp32 scratch
// ---------------------------------------------------------------------------
__device__ float g_h   [BATCH * DM];
__device__ float g_z   [BATCH * DI];        // z half of in_proj output
__device__ float g_xc  [BATCH * DI];
__device__ float g_bc  [BATCH];             // dot(B, C) per row
__device__ float g_yo  [BATCH * DM];
__device__ float g_part[4 * BATCH * 128];   // split-K partials

// ---------------------------------------------------------------------------
// Tiled bf16 operands. Tile = 128 rows x 64 cols = 8192 elems = 16KB,
// SW128-swizzled internally, tiles contiguous: (rb*KT + kb)*8192 elems.
// ---------------------------------------------------------------------------
__device__ __align__(1024) __nv_bfloat16 t_x_hi [BATCH * IN_DIM], t_x_lo [BATCH * IN_DIM];
__device__ __align__(1024) __nv_bfloat16 t_h_hi [BATCH * DM],     t_h_lo [BATCH * DM];
__device__ __align__(1024) __nv_bfloat16 t_xc_hi[BATCH * DI],     t_xc_lo[BATCH * DI];
__device__ __align__(1024) __nv_bfloat16 t_xd_hi[BATCH * 128],    t_xd_lo[BATCH * 128];
__device__ __align__(1024) __nv_bfloat16 t_y_hi [BATCH * DI],     t_y_lo [BATCH * DI];

__device__ __align__(1024) __nv_bfloat16 t_wi_hi[DM * IN_DIM],       t_wi_lo[DM * IN_DIM];
__device__ __align__(1024) __nv_bfloat16 t_wp_hi[NL * 2 * DI * DM],  t_wp_lo[NL * 2 * DI * DM];
__device__ __align__(1024) __nv_bfloat16 t_wx_hi[NL * 128 * DI],     t_wx_lo[NL * 128 * DI];
__device__ __align__(1024) __nv_bfloat16 t_wd_hi[NL * DI * DTR],     t_wd_lo[NL * DI * DTR];
__device__ __align__(1024) __nv_bfloat16 t_wo_hi[NL * DM * DI],      t_wo_lo[NL * DM * DI];
__device__ __align__(1024) __nv_bfloat16 t_wq_hi[OUT_DIM * DM],      t_wq_lo[OUT_DIM * DM];

// ---------------------------------------------------------------------------
// Tiled addressing: element (row, col) of [R, Kpad], KT = Kpad/64.
// ---------------------------------------------------------------------------
__device__ __forceinline__ size_t tiled_off(int row, int col, int KT) {
    size_t tile = (size_t)((row >> 7) * KT + (col >> 6));
    uint32_t inner = (uint32_t)((row & 127) * 128)
                   + (((uint32_t)((col & 63) * 2)) ^ ((uint32_t)(row & 7) << 4));
    return tile * 8192 + (inner >> 1);
}

// ---------------------------------------------------------------------------
// PTX helpers
// ---------------------------------------------------------------------------
__device__ __forceinline__ uint32_t smem_u32(const void* p) {
    uint32_t a;
    asm("{ .reg .u64 t; cvta.to.shared.u64 t, %1; cvt.u32.u64 %0, t; }" : "=r"(a) : "l"(p));
    return a;
}
#define MBARRIER_INIT(a, c) \
    asm volatile("mbarrier.init.shared.b64 [%0], %1;" :: "r"((uint32_t)(a)), "r"((uint32_t)(c)) : "memory")
#define MBAR_EXPECT(a, n) \
    asm volatile("mbarrier.arrive.expect_tx.shared.b64 _, [%0], %1;" :: "r"((uint32_t)(a)), "r"((uint32_t)(n)) : "memory")
#define MBAR_ARRIVE(a) \
    asm volatile("mbarrier.arrive.shared.b64 _, [%0];" :: "r"((uint32_t)(a)) : "memory")
#define CP_BULK(sdst, gsrc, nbytes, bar) \
    asm volatile("cp.async.bulk.shared::cta.global.mbarrier::complete_tx::bytes [%0], [%1], %2, [%3];" \
                 :: "r"((uint32_t)(sdst)), "l"(gsrc), "r"((uint32_t)(nbytes)), "r"((uint32_t)(bar)) : "memory")
#define MBARRIER_WAIT_PARITY(mbar_smem_addr, phase_parity) do { \
    uint32_t _mbar = (uint32_t)(mbar_smem_addr); \
    uint32_t _parity = (uint32_t)(phase_parity); \
    uint32_t _done; \
    asm volatile("{\n\t.reg .pred p;\n\t" \
        "mbarrier.try_wait.parity.acquire.cta.shared::cta.b64 p, [%1], %2;\n\t" \
        "selp.b32 %0, 1, 0, p;\n\t}" : "=r"(_done) : "r"(_mbar), "r"(_parity) : "memory"); \
    if (!_done) { \
        asm volatile("{\n\t.reg .pred P1;\n\t" \
            "WAIT_LOOP_%=:\n\t" \
            "mbarrier.try_wait.parity.acquire.cta.shared::cta.b64 P1, [%0], %1, 0x989680;\n\t" \
            "@P1 bra.uni WAIT_DONE_%=;\n\t" \
            "bra.uni WAIT_LOOP_%=;\n\t" \
            "WAIT_DONE_%=:\n\t}" :: "r"(_mbar), "r"(_parity) : "memory"); \
    } \
} while (0)

__device__ __forceinline__ void ldsm4(uint32_t& r0, uint32_t& r1, uint32_t& r2, uint32_t& r3,
                                      uint32_t a) {
    asm volatile("ldmatrix.sync.aligned.m8n8.x4.shared.b16 {%0,%1,%2,%3}, [%4];"
                 : "=r"(r0), "=r"(r1), "=r"(r2), "=r"(r3) : "r"(a));
}
__device__ __forceinline__ void mma_bf16(float* c, const uint32_t* a, const uint32_t* b) {
    asm volatile("mma.sync.aligned.m16n8k16.row.col.f32.bf16.bf16.f32 "
                 "{%0,%1,%2,%3}, {%4,%5,%6,%7}, {%8,%9}, {%0,%1,%2,%3};"
                 : "+f"(c[0]), "+f"(c[1]), "+f"(c[2]), "+f"(c[3])
                 : "r"(a[0]), "r"(a[1]), "r"(a[2]), "r"(a[3]), "r"(b[0]), "r"(b[1]));
}
__device__ __forceinline__ float siluf(float v) { return v / (1.f + expf(-v)); }
__device__ __forceinline__ float softplusf(float v) {
    return (v > 20.f) ? v : log1pf(expf(v));
}
__device__ __forceinline__ void split_store(__nv_bfloat16* hi, __nv_bfloat16* lo,
                                            size_t off, float v0, float v1) {
    __nv_bfloat16 h0 = __float2bfloat16(v0), h1 = __float2bfloat16(v1);
    __nv_bfloat162 ph = {h0, h1};
    __nv_bfloat162 pl = {__float2bfloat16(v0 - __bfloat162float(h0)),
                         __float2bfloat16(v1 - __bfloat162float(h1))};
    *(__nv_bfloat162*)(hi + off) = ph;
    *(__nv_bfloat162*)(lo + off) = pl;
}

// ---------------------------------------------------------------------------
// bf16x3 GEMM, bulk-copy 3-stage pipeline, full/empty mbarriers.
// CTA 128x128, BK=64, 256 threads. blockIdx.z = K-slice (split-K).
// mode 0: plain (+bias, optional fp32 C, optional tiled hi/lo out)
// mode 1: in_proj epilogue — cols<DI: conv+silu -> g_xc + t_xc; else z -> g_z
// mode 2: dt epilogue — gate: y = xc*(softplus(v+dtb)*bc + Dp)*silu(z) -> t_y
// ---------------------------------------------------------------------------
#define TILE_BYTES 16384
#define STAGE_BYTES (4 * TILE_BYTES)
#define NSTAGE 3
#define GEMM_SMEM (NSTAGE * STAGE_BYTES + 64)

__global__ __launch_bounds__(256, 1)
void gemm_tc(const __nv_bfloat16* __restrict__ Ah, const __nv_bfloat16* __restrict__ Al, int KTa,
             const __nv_bfloat16* __restrict__ Wh, const __nv_bfloat16* __restrict__ Wl, int KTb,
             int niter,
             const float* __restrict__ bias,
             float* __restrict__ C, int N,
             __nv_bfloat16* __restrict__ Chi, __nv_bfloat16* __restrict__ Clo, int NT,
             int mode,
             const float* __restrict__ aux0,   // mode1: conv_w ; mode2: dt_b
             const float* __restrict__ aux1)   // mode1: conv_b ; mode2: D_param
{
    extern __shared__ char smem[];
    const uint32_t sbase = smem_u32(smem);
    const uint32_t sfull = sbase + NSTAGE * STAGE_BYTES;
    const uint32_t sempt = sfull + NSTAGE * 8;

    const int tid  = threadIdx.x;
    const int wid  = tid >> 5;
    const int lane = tid & 31;
    const int rbA = blockIdx.y;
    const int rbB = blockIdx.x;
    const int kOff = blockIdx.z * niter;
    if (C) C += (size_t)blockIdx.z * BATCH * N;

    if (tid == 0) {
        #pragma unroll
        for (int s = 0; s < NSTAGE; s++) {
            MBARRIER_INIT(sfull + s * 8, 1);
            MBARRIER_INIT(sempt + s * 8, 8);
        }
        asm volatile("fence.proxy.async.shared::cta;" ::: "memory");
    }
    __syncthreads();

    const char* pAh = (const char*)Ah;
    const char* pAl = (const char*)Al;
    const char* pWh = (const char*)Wh;
    const char* pWl = (const char*)Wl;

    auto issue = [&](int kb, int s) {
        uint32_t st = sbase + s * STAGE_BYTES;
        uint32_t bar = sfull + s * 8;
        MBAR_EXPECT(bar, 4 * TILE_BYTES);
        size_t oa = ((size_t)(rbA * KTa + kOff + kb)) << 14;
        size_t ob = ((size_t)(rbB * KTb + kOff + kb)) << 14;
        CP_BULK(st,                  pAh + oa, TILE_BYTES, bar);
        CP_BULK(st + TILE_BYTES,     pAl + oa, TILE_BYTES, bar);
        CP_BULK(st + 2 * TILE_BYTES, pWh + ob, TILE_BYTES, bar);
        CP_BULK(st + 3 * TILE_BYTES, pWl + ob, TILE_BYTES, bar);
    };

    if (tid == 0) {
        #pragma unroll
        for (int s = 0; s < NSTAGE; s++)
            if (s < niter) issue(s, s);
    }

    const int lm = lane >> 3;
    const int lr = lane & 7;
    const int wm = (wid >> 2) * 64;
    const int wn = (wid & 3) * 32;
    const uint32_t xmask = (uint32_t)lr << 4;
    const uint32_t arow = (uint32_t)(wm + (lm & 1) * 8 + lr) * 128;
    const uint32_t aseg = (uint32_t)(lm >> 1) * 16;
    const uint32_t brow = (uint32_t)(wn + (lm >> 1) * 8 + lr) * 128;
    const uint32_t bseg = (uint32_t)(lm & 1) * 16;

    float acc[4][4][4];
    #pragma unroll
    for (int i = 0; i < 4; i++)
        #pragma unroll
        for (int j = 0; j < 4; j++)
            #pragma unroll
            for (int q = 0; q < 4; q++) acc[i][j][q] = 0.f;

    for (int kb = 0; kb < niter; kb++) {
        const int s = kb % NSTAGE;
        const int ph = (kb / NSTAGE) & 1;
        MBARRIER_WAIT_PARITY(sfull + s * 8, ph);
        uint32_t st  = sbase + s * STAGE_BYTES;
        uint32_t sAh = st;
        uint32_t sAl = st + TILE_BYTES;
        uint32_t sBh = st + 2 * TILE_BYTES;
        uint32_t sBl = st + 3 * TILE_BYTES;

        #pragma unroll
        for (int kk = 0; kk < 4; kk++) {
            uint32_t ka  = ((uint32_t)(kk * 32) + aseg) ^ xmask;
            uint32_t kbo = ((uint32_t)(kk * 32) + bseg) ^ xmask;
            uint32_t bh[4][2], bl[4][2];
            #pragma unroll
            for (int p = 0; p < 2; p++) {
                ldsm4(bh[2*p][0], bh[2*p][1], bh[2*p+1][0], bh[2*p+1][1],
                      sBh + brow + p * 2048 + kbo);
                ldsm4(bl[2*p][0], bl[2*p][1], bl[2*p+1][0], bl[2*p+1][1],
                      sBl + brow + p * 2048 + kbo);
            }
            #pragma unroll
            for (int mi = 0; mi < 4; mi++) {
                uint32_t ah[4], al[4];
                ldsm4(ah[0], ah[1], ah[2], ah[3], sAh + arow + mi * 2048 + ka);
                ldsm4(al[0], al[1], al[2], al[3], sAl + arow + mi * 2048 + ka);
                #pragma unroll
                for (int ni = 0; ni < 4; ni++) {
                    mma_bf16(acc[mi][ni], ah, bh[ni]);
                    mma_bf16(acc[mi][ni], ah, bl[ni]);
                    mma_bf16(acc[mi][ni], al, bh[ni]);
                }
            }
        }
        if (lane == 0) MBAR_ARRIVE(sempt + s * 8);
        if (tid == 0 && kb + NSTAGE < niter) {
            MBARRIER_WAIT_PARITY(sempt + s * 8, ph);
            issue(kb + NSTAGE, s);
        }
    }

    // ---- epilogue ----
    const int g = lane >> 2, t4 = lane & 3;
    const int bm = rbA * 128, bn = rbB * 128;
    #pragma unroll
    for (int mi = 0; mi < 4; mi++) {
        #pragma unroll
        for (int ni = 0; ni < 4; ni++) {
            int col = bn + wn + ni * 8 + t4 * 2;
            #pragma unroll
            for (int hrow = 0; hrow < 2; hrow++) {
                int row = bm + wm + mi * 16 + g + hrow * 8;
                float v0 = acc[mi][ni][hrow * 2 + 0];
                float v1 = acc[mi][ni][hrow * 2 + 1];
                if (mode == 0) {
                    if (bias && col < N) { v0 += bias[col]; v1 += bias[col + 1]; }
                    if (C && col < N)
                        *(float2*)(C + (size_t)row * N + col) = make_float2(v0, v1);
                    if (Chi)
                        split_store(Chi, Clo, tiled_off(row, col, NT), v0, v1);
                } else if (mode == 1) {
                    if (col < DI) {
                        float c0 = aux1[col]     + v0 * aux0[col * DC + (DC - 1)];
                        float c1 = aux1[col + 1] + v1 * aux0[(col + 1) * DC + (DC - 1)];
                        float x0 = siluf(c0), x1 = siluf(c1);
                        *(float2*)(g_xc + (size_t)row * DI + col) = make_float2(x0, x1);
                        split_store(t_xc_hi, t_xc_lo, tiled_off(row, col, DI / 64), x0, x1);
                    } else {
                        *(float2*)(g_z + (size_t)row * DI + (col - DI)) = make_float2(v0, v1);
                    }
                } else {
                    float bcv = g_bc[row];
                    float2 xc2 = *(const float2*)(g_xc + (size_t)row * DI + col);
                    float2 z2  = *(const float2*)(g_z  + (size_t)row * DI + col);
                    float dt0 = softplusf(v0 + aux0[col]);
                    float dt1 = softplusf(v1 + aux0[col + 1]);
                    float y0 = xc2.x * (dt0 * bcv + aux1[col])     * siluf(z2.x);
                    float y1 = xc2.y * (dt1 * bcv + aux1[col + 1]) * siluf(z2.y);
                    split_store(t_y_hi, t_y_lo, tiled_off(row, col, DI / 64), y0, y1);
                }
            }
        }
    }
}

// ---------------------------------------------------------------------------
// Split-K reduce for xproj: emit tiled hi/lo for dt cols + bc = dot(B,C)
// ---------------------------------------------------------------------------
__global__ void reduce_xdbl_kernel()
{
    int row = blockIdx.x;
    int t = threadIdx.x;   // 128
    __shared__ float sv[128];
    float v = g_part[(size_t)row * 128 + t]
            + g_part[(size_t)BATCH * 128     + (size_t)row * 128 + t]
            + g_part[(size_t)BATCH * 128 * 2 + (size_t)row * 128 + t]
            + g_part[(size_t)BATCH * 128 * 3 + (size_t)row * 128 + t];
    sv[t] = v;
    if (t < DTR) {
        __nv_bfloat16 h = __float2bfloat16(v);
        size_t to = tiled_off(row, t, 2);
        t_xd_hi[to] = h;
        t_xd_lo[to] = __float2bfloat16(v - __bfloat162float(h));
    }
    __syncthreads();
    if (t == 0) {
        float bc = 0.f;
        #pragma unroll
        for (int i = 0; i < DS; i++) bc += sv[DTR + i] * sv[DTR + DS + i];
        g_bc[row] = bc;
    }
}

// ---------------------------------------------------------------------------
// Split-K reduce for final projection
// ---------------------------------------------------------------------------
__global__ void reduce_out_kernel(const float* __restrict__ bias,
                                  float* __restrict__ out)
{
    int row = blockIdx.x;
    int t = threadIdx.x;     // 128 = OUT_DIM
    float v = bias[t]
            + g_part[(size_t)row * 128 + t]
            + g_part[(size_t)BATCH * 128     + (size_t)row * 128 + t]
            + g_part[(size_t)BATCH * 128 * 2 + (size_t)row * 128 + t]
            + g_part[(size_t)BATCH * 128 * 3 + (size_t)row * 128 + t];
    out[(size_t)row * OUT_DIM + t] = v;
}

// ---------------------------------------------------------------------------
// fp32 [R,K] -> tiled+swizzled bf16 hi/lo
// ---------------------------------------------------------------------------
__global__ void cvt_tiled(const float* __restrict__ src,
                          __nv_bfloat16* __restrict__ hi,
                          __nv_bfloat16* __restrict__ lo,
                          int R, int k8, int KT)
{
    int idx = blockIdx.x * 256 + threadIdx.x;
    if (idx >= R * k8) return;
    int row = idx / k8;
    int k = (idx - row * k8) * 8;
    const float4* s = (const float4*)(src + (size_t)row * (k8 * 8) + k);
    float4 v0 = s[0], v1 = s[1];
    float f[8] = {v0.x, v0.y, v0.z, v0.w, v1.x, v1.y, v1.z, v1.w};
    uint32_t ph[4], pl[4];
    #pragma unroll
    for (int j = 0; j < 4; j++) {
        float a = f[2*j], b = f[2*j+1];
        __nv_bfloat16 ha = __float2bfloat16(a), hb = __float2bfloat16(b);
        __nv_bfloat162 vh = {ha, hb};
        __nv_bfloat162 vl = {__float2bfloat16(a - __bfloat162float(ha)),
                             __float2bfloat16(b - __bfloat162float(hb))};
        ph[j] = *(uint32_t*)&vh;
        pl[j] = *(uint32_t*)&vl;
    }
    size_t to = tiled_off(row, k, KT);
    *(uint4*)(hi + to) = make_uint4(ph[0], ph[1], ph[2], ph[3]);
    *(uint4*)(lo + to) = make_uint4(pl[0], pl[1], pl[2], pl[3]);
}

// ---------------------------------------------------------------------------
// h += LN(yo)*g + b; fp32 h + tiled hi/lo
// ---------------------------------------------------------------------------
__global__ void ln_res_kernel(const float* __restrict__ gam,
                              const float* __restrict__ bet)
{
    int b = blockIdx.x;
    int t = threadIdx.x;
    __shared__ float sa[8], sbs[8], smu, sinv;
    int d = t * 4;
    float4 v4 = *(const float4*)(g_yo + (size_t)b * DM + d);
    float vv[4] = {v4.x, v4.y, v4.z, v4.w};
    float s = vv[0] + vv[1] + vv[2] + vv[3];
    float s2 = vv[0]*vv[0] + vv[1]*vv[1] + vv[2]*vv[2] + vv[3]*vv[3];
    int lane = t & 31, w = t >> 5;
    #pragma unroll
    for (int o = 16; o; o >>= 1) {
        s  += __shfl_down_sync(0xffffffffu, s,  o);
        s2 += __shfl_down_sync(0xffffffffu, s2, o);
    }
    if (lane == 0) { sa[w] = s; sbs[w] = s2; }
    __syncthreads();
    if (w == 0) {
        s  = (lane < 8) ? sa[lane] : 0.f;
        s2 = (lane < 8) ? sbs[lane] : 0.f;
        #pragma unroll
        for (int o = 4; o; o >>= 1) {
            s  += __shfl_down_sync(0xffffffffu, s,  o);
            s2 += __shfl_down_sync(0xffffffffu, s2, o);
        }
        if (lane == 0) {
            float mu = s / DM;
            float var = s2 / DM - mu * mu;
            smu = mu;
            sinv = rsqrtf(var + 1e-5f);
        }
    }
    __syncthreads();
    float mu = smu, inv = sinv;
    float hv[4];
    #pragma unroll
    for (int j = 0; j < 4; j++) {
        size_t o = (size_t)b * DM + d + j;
        hv[j] = g_h[o] + (vv[j] - mu) * inv * gam[d + j] + bet[d + j];
        g_h[o] = hv[j];
    }
    uint32_t ph[2], pl[2];
    #pragma unroll
    for (int j = 0; j < 2; j++) {
        __nv_bfloat16 ha = __float2bfloat16(hv[2*j]), hb = __float2bfloat16(hv[2*j+1]);
        __nv_bfloat162 vh = {ha, hb};
        __nv_bfloat162 vl = {__float2bfloat16(hv[2*j]   - __bfloat162float(ha)),
                             __float2bfloat16(hv[2*j+1] - __bfloat162float(hb))};
        ph[j] = *(uint32_t*)&vh; pl[j] = *(uint32_t*)&vl;
    }
    size_t to = tiled_off(b, d, DM / 64);
    *(uint2*)(t_h_hi + to) = make_uint2(ph[0], ph[1]);
    *(uint2*)(t_h_lo + to) = make_uint2(pl[0], pl[1]);
}

// ---------------------------------------------------------------------------
// Host launcher
// ---------------------------------------------------------------------------
extern "C" void kernel_launch(void* const* d_in, const int* in_sizes, int n_in,
                              void* d_out, int out_size)
{
    const float* x        = (const float*)d_in[0];
    const float* inp_w    = (const float*)d_in[1];
    const float* inp_b    = (const float*)d_in[2];
    const float* in_proj  = (const float*)d_in[3];
    const float* conv_w   = (const float*)d_in[4];
    const float* conv_b   = (const float*)d_in[5];
    const float* xproj_w  = (const float*)d_in[6];
    const float* dt_w     = (const float*)d_in[7];
    const float* dt_b     = (const float*)d_in[8];
    // d_in[9] = A_log : dead (h0 == 0, single scan step)
    const float* D_param  = (const float*)d_in[10];
    const float* out_w    = (const float*)d_in[11];
    const float* ln_g     = (const float*)d_in[12];
    const float* ln_b     = (const float*)d_in[13];
    const float* outp_w   = (const float*)d_in[14];
    const float* outp_b   = (const float*)d_in[15];
    float* out = (float*)d_out;

    float *p_h, *p_yo, *p_part;
    cudaGetSymbolAddress((void**)&p_h,    g_h);
    cudaGetSymbolAddress((void**)&p_yo,   g_yo);
    cudaGetSymbolAddress((void**)&p_part, g_part);

    __nv_bfloat16 *xh, *xl, *hh, *hl, *xch, *xcl, *xdh, *xdl, *yh, *yl;
    cudaGetSymbolAddress((void**)&xh,  t_x_hi);  cudaGetSymbolAddress((void**)&xl,  t_x_lo);
    cudaGetSymbolAddress((void**)&hh,  t_h_hi);  cudaGetSymbolAddress((void**)&hl,  t_h_lo);
    cudaGetSymbolAddress((void**)&xch, t_xc_hi); cudaGetSymbolAddress((void**)&xcl, t_xc_lo);
    cudaGetSymbolAddress((void**)&xdh, t_xd_hi); cudaGetSymbolAddress((void**)&xdl, t_xd_lo);
    cudaGetSymbolAddress((void**)&yh,  t_y_hi);  cudaGetSymbolAddress((void**)&yl,  t_y_lo);

    __nv_bfloat16 *wih, *wil, *wph, *wpl, *wxh, *wxl, *wdh, *wdl, *woh, *wol, *wqh, *wql;
    cudaGetSymbolAddress((void**)&wih, t_wi_hi); cudaGetSymbolAddress((void**)&wil, t_wi_lo);
    cudaGetSymbolAddress((void**)&wph, t_wp_hi); cudaGetSymbolAddress((void**)&wpl, t_wp_lo);
    cudaGetSymbolAddress((void**)&wxh, t_wx_hi); cudaGetSymbolAddress((void**)&wxl, t_wx_lo);
    cudaGetSymbolAddress((void**)&wdh, t_wd_hi); cudaGetSymbolAddress((void**)&wdl, t_wd_lo);
    cudaGetSymbolAddress((void**)&woh, t_wo_hi); cudaGetSymbolAddress((void**)&wol, t_wo_lo);
    cudaGetSymbolAddress((void**)&wqh, t_wq_hi); cudaGetSymbolAddress((void**)&wql, t_wq_lo);

    cudaFuncSetAttribute(gemm_tc, cudaFuncAttributeMaxDynamicSharedMemorySize, GEMM_SMEM);

    auto cvt = [](const float* s, __nv_bfloat16* h, __nv_bfloat16* l, int R, int K) {
        int n = R * (K / 8);
        cvt_tiled<<<(n + 255) / 256, 256>>>(s, h, l, R, K / 8, K / 64);
    };
    cvt(x,       xh,  xl,  BATCH, IN_DIM);
    cvt(inp_w,   wih, wil, DM, IN_DIM);
    cvt(in_proj, wph, wpl, NL * 2 * DI, DM);
    for (int l = 0; l < NL; l++)
        cvt(xproj_w + (size_t)l * XD * DI, wxh + (size_t)l * 128 * DI,
            wxl + (size_t)l * 128 * DI, XD, DI);
    cvt(dt_w,    wdh, wdl, NL * DI, DTR);
    cvt(out_w,   woh, wol, NL * DM, DI);
    cvt(outp_w,  wqh, wql, OUT_DIM, DM);

    dim3 blk(256);

    // h = x @ inp_w^T + inp_b  (emits tiled hi/lo)
    gemm_tc<<<dim3(DM/128, BATCH/128, 1), blk, GEMM_SMEM>>>(
        xh, xl, IN_DIM/64, wih, wil, IN_DIM/64, IN_DIM/64,
        inp_b, p_h, DM, hh, hl, DM/64, 0, nullptr, nullptr);

    for (int l = 0; l < NL; l++) {
        const __nv_bfloat16* iph = wph + (size_t)l * 2 * DI * DM;
        const __nv_bfloat16* ipl = wpl + (size_t)l * 2 * DI * DM;
        const __nv_bfloat16* xpj = wxh + (size_t)l * 128 * DI;
        const __nv_bfloat16* xpl2= wxl + (size_t)l * 128 * DI;
        const __nv_bfloat16* dth = wdh + (size_t)l * DI * DTR;
        const __nv_bfloat16* dtl = wdl + (size_t)l * DI * DTR;
        const __nv_bfloat16* ohh = woh + (size_t)l * DM * DI;
        const __nv_bfloat16* oll = wol + (size_t)l * DM * DI;
        const float* cw  = conv_w  + (size_t)l * DI * DC;
        const float* cb  = conv_b  + (size_t)l * DI;
        const float* dtb = dt_b    + (size_t)l * DI;
        const float* Dp  = D_param + (size_t)l * DI;
        const float* lg  = ln_g    + (size_t)l * DM;
        const float* lb  = ln_b    + (size_t)l * DM;

        // xz GEMM with fused conv+silu epilogue (mode 1)
        gemm_tc<<<dim3(2*DI/128, BATCH/128, 1), blk, GEMM_SMEM>>>(
            hh, hl, DM/64, iph, ipl, DM/64, DM/64,
            nullptr, nullptr, 2*DI, nullptr, nullptr, 0, 1, cw, cb);
        // x_dbl partials: split-K x4 (each K=512)
        gemm_tc<<<dim3(1, BATCH/128, 4), blk, GEMM_SMEM>>>(
            xch, xcl, DI/64, xpj, xpl2, DI/64, (DI/64)/4,
            nullptr, p_part, 128, nullptr, nullptr, 0, 0, nullptr, nullptr);
        reduce_xdbl_kernel<<<BATCH, 128>>>();
        // dt GEMM with fused gate epilogue (mode 2)
        gemm_tc<<<dim3(DI/128, BATCH/128, 1), blk, GEMM_SMEM>>>(
            xdh, xdl, 2, dth, dtl, 1, 1,
            nullptr, nullptr, DI, nullptr, nullptr, 0, 2, dtb, Dp);
        // yo = y @ out_w^T
        gemm_tc<<<dim3(DM/128, BATCH/128, 1), blk, GEMM_SMEM>>>(
            yh, yl, DI/64, ohh, oll, DI/64, DI/64,
            nullptr, p_yo, DM, nullptr, nullptr, 0, 0, nullptr, nullptr);
        ln_res_kernel<<<BATCH, 256>>>(lg, lb);
    }

    // out partials: split-K x4 (each K=256), then reduce + bias
    gemm_tc<<<dim3(1, BATCH/128, 4), blk, GEMM_SMEM>>>(
        hh, hl, DM/64, wqh, wql, DM/64, (DM/64)/4,
        nullptr, p_part, 128, nullptr, nullptr, 0, 0, nullptr, nullptr);
    reduce_out_kernel<<<BATCH, 128>>>(outp_b, out);
    (void)in_sizes; (void)n_in; (void)out_size;
}

// round 9
// speedup vs baseline: 1.0299x; 1.0299x over previous
#include <cuda_runtime.h>
#include <cuda_bf16.h>
#include <cstdint>
#include <math.h>

// Problem constants
#define NL  4
#define DM  1024
#define DI  2048
#define DS  16
#define DC  4
#define DTR 64
#define IN_DIM  256
#define OUT_DIM 128
#define BATCH 4096
#define XD 96          // DTR + 2*DS

// ---------------------------------------------------------------------------
// fp32 scratch
// ---------------------------------------------------------------------------
__device__ float g_h   [BATCH * DM];
__device__ float g_z   [BATCH * DI];        // z half of in_proj output
__device__ float g_xc  [BATCH * DI];
__device__ float g_bc  [BATCH];             // dot(B, C) per row
__device__ float g_yo  [BATCH * DM];
__device__ float g_part[4 * BATCH * 128];   // split-K partials
__device__ float2 g_cvp[NL * DI];           // (conv_b, conv_w[:,DC-1])
__device__ float2 g_dtq[NL * DI];           // (dt_b, D_param)

// ---------------------------------------------------------------------------
// Tiled bf16 operands. Tile = 128 rows x 64 cols = 16KB, SW128-swizzled.
// ---------------------------------------------------------------------------
__device__ __align__(1024) __nv_bfloat16 t_x_hi [BATCH * IN_DIM], t_x_lo [BATCH * IN_DIM];
__device__ __align__(1024) __nv_bfloat16 t_h_hi [BATCH * DM],     t_h_lo [BATCH * DM];
__device__ __align__(1024) __nv_bfloat16 t_xc_hi[BATCH * DI],     t_xc_lo[BATCH * DI];
__device__ __align__(1024) __nv_bfloat16 t_xd_hi[BATCH * 128],    t_xd_lo[BATCH * 128];
__device__ __align__(1024) __nv_bfloat16 t_y_hi [BATCH * DI],     t_y_lo [BATCH * DI];

__device__ __align__(1024) __nv_bfloat16 t_wi_hi[DM * IN_DIM],       t_wi_lo[DM * IN_DIM];
__device__ __align__(1024) __nv_bfloat16 t_wp_hi[NL * 2 * DI * DM],  t_wp_lo[NL * 2 * DI * DM];
__device__ __align__(1024) __nv_bfloat16 t_wx_hi[NL * 128 * DI],     t_wx_lo[NL * 128 * DI];
__device__ __align__(1024) __nv_bfloat16 t_wd_hi[NL * DI * DTR],     t_wd_lo[NL * DI * DTR];
__device__ __align__(1024) __nv_bfloat16 t_wo_hi[NL * DM * DI],      t_wo_lo[NL * DM * DI];
__device__ __align__(1024) __nv_bfloat16 t_wq_hi[OUT_DIM * DM],      t_wq_lo[OUT_DIM * DM];

// ---------------------------------------------------------------------------
// Tiled addressing
// ---------------------------------------------------------------------------
__device__ __forceinline__ size_t tiled_off(int row, int col, int KT) {
    size_t tile = (size_t)((row >> 7) * KT + (col >> 6));
    uint32_t inner = (uint32_t)((row & 127) * 128)
                   + (((uint32_t)((col & 63) * 2)) ^ ((uint32_t)(row & 7) << 4));
    return tile * 8192 + (inner >> 1);
}

// ---------------------------------------------------------------------------
// PTX helpers
// ---------------------------------------------------------------------------
__device__ __forceinline__ uint32_t smem_u32(const void* p) {
    uint32_t a;
    asm("{ .reg .u64 t; cvta.to.shared.u64 t, %1; cvt.u32.u64 %0, t; }" : "=r"(a) : "l"(p));
    return a;
}
#define MBARRIER_INIT(a, c) \
    asm volatile("mbarrier.init.shared.b64 [%0], %1;" :: "r"((uint32_t)(a)), "r"((uint32_t)(c)) : "memory")
#define MBAR_EXPECT(a, n) \
    asm volatile("mbarrier.arrive.expect_tx.shared.b64 _, [%0], %1;" :: "r"((uint32_t)(a)), "r"((uint32_t)(n)) : "memory")
#define MBAR_ARRIVE(a) \
    asm volatile("mbarrier.arrive.shared.b64 _, [%0];" :: "r"((uint32_t)(a)) : "memory")
#define CP_BULK(sdst, gsrc, nbytes, bar) \
    asm volatile("cp.async.bulk.shared::cta.global.mbarrier::complete_tx::bytes [%0], [%1], %2, [%3];" \
                 :: "r"((uint32_t)(sdst)), "l"(gsrc), "r"((uint32_t)(nbytes)), "r"((uint32_t)(bar)) : "memory")
#define MBARRIER_WAIT_PARITY(mbar_smem_addr, phase_parity) do { \
    uint32_t _mbar = (uint32_t)(mbar_smem_addr); \
    uint32_t _parity = (uint32_t)(phase_parity); \
    uint32_t _done; \
    asm volatile("{\n\t.reg .pred p;\n\t" \
        "mbarrier.try_wait.parity.acquire.cta.shared::cta.b64 p, [%1], %2;\n\t" \
        "selp.b32 %0, 1, 0, p;\n\t}" : "=r"(_done) : "r"(_mbar), "r"(_parity) : "memory"); \
    if (!_done) { \
        asm volatile("{\n\t.reg .pred P1;\n\t" \
            "WAIT_LOOP_%=:\n\t" \
            "mbarrier.try_wait.parity.acquire.cta.shared::cta.b64 P1, [%0], %1, 0x989680;\n\t" \
            "@P1 bra.uni WAIT_DONE_%=;\n\t" \
            "bra.uni WAIT_LOOP_%=;\n\t" \
            "WAIT_DONE_%=:\n\t}" :: "r"(_mbar), "r"(_parity) : "memory"); \
    } \
} while (0)

__device__ __forceinline__ void ldsm4(uint32_t& r0, uint32_t& r1, uint32_t& r2, uint32_t& r3,
                                      uint32_t a) {
    asm volatile("ldmatrix.sync.aligned.m8n8.x4.shared.b16 {%0,%1,%2,%3}, [%4];"
                 : "=r"(r0), "=r"(r1), "=r"(r2), "=r"(r3) : "r"(a));
}
__device__ __forceinline__ void mma_bf16(float* c, const uint32_t* a, const uint32_t* b) {
    asm volatile("mma.sync.aligned.m16n8k16.row.col.f32.bf16.bf16.f32 "
                 "{%0,%1,%2,%3}, {%4,%5,%6,%7}, {%8,%9}, {%0,%1,%2,%3};"
                 : "+f"(c[0]), "+f"(c[1]), "+f"(c[2]), "+f"(c[3])
                 : "r"(a[0]), "r"(a[1]), "r"(a[2]), "r"(a[3]), "r"(b[0]), "r"(b[1]));
}
__device__ __forceinline__ float siluf(float v) { return v / (1.f + expf(-v)); }
__device__ __forceinline__ float softplusf(float v) {
    return (v > 20.f) ? v : log1pf(expf(v));
}
__device__ __forceinline__ void split_store(__nv_bfloat16* hi, __nv_bfloat16* lo,
                                            size_t off, float v0, float v1) {
    __nv_bfloat16 h0 = __float2bfloat16(v0), h1 = __float2bfloat16(v1);
    __nv_bfloat162 ph = {h0, h1};
    __nv_bfloat162 pl = {__float2bfloat16(v0 - __bfloat162float(h0)),
                         __float2bfloat16(v1 - __bfloat162float(h1))};
    *(__nv_bfloat162*)(hi + off) = ph;
    *(__nv_bfloat162*)(lo + off) = pl;
}

// ---------------------------------------------------------------------------
// bf16x3 GEMM, bulk-copy 3-stage pipeline, full/empty mbarriers.
// Compile-time MODE:
//   0: plain (+bias, optional fp32 C, optional tiled hi/lo out)
//   1: in_proj epilogue — cols<DI: conv+silu -> g_xc + t_xc; else z -> g_z
//      (aux = g_cvp + l*DI, packed (cb, cw3))
//   2: dt epilogue — y = xc*(softplus(v+dtb)*bc + Dp)*silu(z) -> t_y
//      (aux = g_dtq + l*DI, packed (dtb, Dp))
// ---------------------------------------------------------------------------
#define TILE_BYTES 16384
#define STAGE_BYTES (4 * TILE_BYTES)
#define NSTAGE 3
#define GEMM_SMEM (NSTAGE * STAGE_BYTES + 64)

template<int MODE>
__global__ __launch_bounds__(256, 1)
void gemm_tc(const __nv_bfloat16* __restrict__ Ah, const __nv_bfloat16* __restrict__ Al, int KTa,
             const __nv_bfloat16* __restrict__ Wh, const __nv_bfloat16* __restrict__ Wl, int KTb,
             int niter,
             const float* __restrict__ bias,
             float* __restrict__ C, int N,
             __nv_bfloat16* __restrict__ Chi, __nv_bfloat16* __restrict__ Clo, int NT,
             const float2* __restrict__ aux)
{
    extern __shared__ char smem[];
    const uint32_t sbase = smem_u32(smem);
    const uint32_t sfull = sbase + NSTAGE * STAGE_BYTES;
    const uint32_t sempt = sfull + NSTAGE * 8;

    const int tid  = threadIdx.x;
    const int wid  = tid >> 5;
    const int lane = tid & 31;
    const int rbA = blockIdx.y;
    const int rbB = blockIdx.x;
    const int kOff = blockIdx.z * niter;
    if (MODE == 0 && C) C += (size_t)blockIdx.z * BATCH * N;

    if (tid == 0) {
        #pragma unroll
        for (int s = 0; s < NSTAGE; s++) {
            MBARRIER_INIT(sfull + s * 8, 1);
            MBARRIER_INIT(sempt + s * 8, 8);
        }
        asm volatile("fence.proxy.async.shared::cta;" ::: "memory");
    }
    __syncthreads();

    const char* pAh = (const char*)Ah;
    const char* pAl = (const char*)Al;
    const char* pWh = (const char*)Wh;
    const char* pWl = (const char*)Wl;

    auto issue = [&](int kb, int s) {
        uint32_t st = sbase + s * STAGE_BYTES;
        uint32_t bar = sfull + s * 8;
        MBAR_EXPECT(bar, 4 * TILE_BYTES);
        size_t oa = ((size_t)(rbA * KTa + kOff + kb)) << 14;
        size_t ob = ((size_t)(rbB * KTb + kOff + kb)) << 14;
        CP_BULK(st,                  pAh + oa, TILE_BYTES, bar);
        CP_BULK(st + TILE_BYTES,     pAl + oa, TILE_BYTES, bar);
        CP_BULK(st + 2 * TILE_BYTES, pWh + ob, TILE_BYTES, bar);
        CP_BULK(st + 3 * TILE_BYTES, pWl + ob, TILE_BYTES, bar);
    };

    if (tid == 0) {
        #pragma unroll
        for (int s = 0; s < NSTAGE; s++)
            if (s < niter) issue(s, s);
    }

    const int lm = lane >> 3;
    const int lr = lane & 7;
    const int wm = (wid >> 2) * 64;
    const int wn = (wid & 3) * 32;
    const uint32_t xmask = (uint32_t)lr << 4;
    const uint32_t arow = (uint32_t)(wm + (lm & 1) * 8 + lr) * 128;
    const uint32_t aseg = (uint32_t)(lm >> 1) * 16;
    const uint32_t brow = (uint32_t)(wn + (lm >> 1) * 8 + lr) * 128;
    const uint32_t bseg = (uint32_t)(lm & 1) * 16;

    float acc[4][4][4];
    #pragma unroll
    for (int i = 0; i < 4; i++)
        #pragma unroll
        for (int j = 0; j < 4; j++)
            #pragma unroll
            for (int q = 0; q < 4; q++) acc[i][j][q] = 0.f;

    for (int kb = 0; kb < niter; kb++) {
        const int s = kb % NSTAGE;
        const int ph = (kb / NSTAGE) & 1;
        MBARRIER_WAIT_PARITY(sfull + s * 8, ph);
        uint32_t st  = sbase + s * STAGE_BYTES;
        uint32_t sAh = st;
        uint32_t sAl = st + TILE_BYTES;
        uint32_t sBh = st + 2 * TILE_BYTES;
        uint32_t sBl = st + 3 * TILE_BYTES;

        #pragma unroll
        for (int kk = 0; kk < 4; kk++) {
            uint32_t ka  = ((uint32_t)(kk * 32) + aseg) ^ xmask;
            uint32_t kbo = ((uint32_t)(kk * 32) + bseg) ^ xmask;
            uint32_t bh[4][2], bl[4][2];
            #pragma unroll
            for (int p = 0; p < 2; p++) {
                ldsm4(bh[2*p][0], bh[2*p][1], bh[2*p+1][0], bh[2*p+1][1],
                      sBh + brow + p * 2048 + kbo);
                ldsm4(bl[2*p][0], bl[2*p][1], bl[2*p+1][0], bl[2*p+1][1],
                      sBl + brow + p * 2048 + kbo);
            }
            #pragma unroll
            for (int mi = 0; mi < 4; mi++) {
                uint32_t ah[4], al[4];
                ldsm4(ah[0], ah[1], ah[2], ah[3], sAh + arow + mi * 2048 + ka);
                ldsm4(al[0], al[1], al[2], al[3], sAl + arow + mi * 2048 + ka);
                #pragma unroll
                for (int ni = 0; ni < 4; ni++) {
                    mma_bf16(acc[mi][ni], ah, bh[ni]);
                    mma_bf16(acc[mi][ni], ah, bl[ni]);
                    mma_bf16(acc[mi][ni], al, bh[ni]);
                }
            }
        }
        if (lane == 0) MBAR_ARRIVE(sempt + s * 8);
        if (tid == 0 && kb + NSTAGE < niter) {
            MBARRIER_WAIT_PARITY(sempt + s * 8, ph);
            issue(kb + NSTAGE, s);
        }
    }

    // ---- epilogue ----
    const int g = lane >> 2, t4 = lane & 3;
    const int bm = rbA * 128, bn = rbB * 128;
    #pragma unroll
    for (int mi = 0; mi < 4; mi++) {
        #pragma unroll
        for (int ni = 0; ni < 4; ni++) {
            int col = bn + wn + ni * 8 + t4 * 2;
            #pragma unroll
            for (int hrow = 0; hrow < 2; hrow++) {
                int row = bm + wm + mi * 16 + g + hrow * 8;
                float v0 = acc[mi][ni][hrow * 2 + 0];
                float v1 = acc[mi][ni][hrow * 2 + 1];
                if (MODE == 0) {
                    if (bias && col < N) { v0 += bias[col]; v1 += bias[col + 1]; }
                    if (C && col < N)
                        *(float2*)(C + (size_t)row * N + col) = make_float2(v0, v1);
                    if (Chi)
                        split_store(Chi, Clo, tiled_off(row, col, NT), v0, v1);
                } else if (MODE == 1) {
                    if (col < DI) {
                        float2 a0 = aux[col], a1 = aux[col + 1];
                        float x0 = siluf(a0.x + v0 * a0.y);
                        float x1 = siluf(a1.x + v1 * a1.y);
                        *(float2*)(g_xc + (size_t)row * DI + col) = make_float2(x0, x1);
                        split_store(t_xc_hi, t_xc_lo, tiled_off(row, col, DI / 64), x0, x1);
                    } else {
                        *(float2*)(g_z + (size_t)row * DI + (col - DI)) = make_float2(v0, v1);
                    }
                } else {
                    float bcv = g_bc[row];
                    float2 xc2 = *(const float2*)(g_xc + (size_t)row * DI + col);
                    float2 z2  = *(const float2*)(g_z  + (size_t)row * DI + col);
                    float2 a0 = aux[col], a1 = aux[col + 1];
                    float y0 = xc2.x * (softplusf(v0 + a0.x) * bcv + a0.y) * siluf(z2.x);
                    float y1 = xc2.y * (softplusf(v1 + a1.x) * bcv + a1.y) * siluf(z2.y);
                    split_store(t_y_hi, t_y_lo, tiled_off(row, col, DI / 64), y0, y1);
                }
            }
        }
    }
}

// ---------------------------------------------------------------------------
// pack aux: g_cvp = (conv_b, conv_w[:,DC-1]), g_dtq = (dt_b, D_param)
// ---------------------------------------------------------------------------
__global__ void pack_aux_kernel(const float* __restrict__ cw, const float* __restrict__ cb,
                                const float* __restrict__ dtb, const float* __restrict__ Dp)
{
    int i = blockIdx.x * 256 + threadIdx.x;      // NL*DI total
    if (i >= NL * DI) return;
    g_cvp[i] = make_float2(cb[i], cw[i * DC + (DC - 1)]);
    g_dtq[i] = make_float2(dtb[i], Dp[i]);
}

// ---------------------------------------------------------------------------
// Split-K reduce for xproj: emit tiled hi/lo for dt cols + bc = dot(B,C)
// ---------------------------------------------------------------------------
__global__ void reduce_xdbl_kernel()
{
    int row = blockIdx.x;
    int t = threadIdx.x;   // 128
    __shared__ float sv[128];
    float v = g_part[(size_t)row * 128 + t]
            + g_part[(size_t)BATCH * 128     + (size_t)row * 128 + t]
            + g_part[(size_t)BATCH * 128 * 2 + (size_t)row * 128 + t]
            + g_part[(size_t)BATCH * 128 * 3 + (size_t)row * 128 + t];
    sv[t] = v;
    if (t < DTR) {
        __nv_bfloat16 h = __float2bfloat16(v);
        size_t to = tiled_off(row, t, 2);
        t_xd_hi[to] = h;
        t_xd_lo[to] = __float2bfloat16(v - __bfloat162float(h));
    }
    __syncthreads();
    if (t == 0) {
        float bc = 0.f;
        #pragma unroll
        for (int i = 0; i < DS; i++) bc += sv[DTR + i] * sv[DTR + DS + i];
        g_bc[row] = bc;
    }
}

// ---------------------------------------------------------------------------
// Split-K reduce for final projection
// ---------------------------------------------------------------------------
__global__ void reduce_out_kernel(const float* __restrict__ bias,
                                  float* __restrict__ out)
{
    int row = blockIdx.x;
    int t = threadIdx.x;     // 128 = OUT_DIM
    float v = bias[t]
            + g_part[(size_t)row * 128 + t]
            + g_part[(size_t)BATCH * 128     + (size_t)row * 128 + t]
            + g_part[(size_t)BATCH * 128 * 2 + (size_t)row * 128 + t]
            + g_part[(size_t)BATCH * 128 * 3 + (size_t)row * 128 + t];
    out[(size_t)row * OUT_DIM + t] = v;
}

// ---------------------------------------------------------------------------
// fp32 [R,K] -> tiled+swizzled bf16 hi/lo
// ---------------------------------------------------------------------------
__global__ void cvt_tiled(const float* __restrict__ src,
                          __nv_bfloat16* __restrict__ hi,
                          __nv_bfloat16* __restrict__ lo,
                          int R, int k8, int KT)
{
    int idx = blockIdx.x * 256 + threadIdx.x;
    if (idx >= R * k8) return;
    int row = idx / k8;
    int k = (idx - row * k8) * 8;
    const float4* s = (const float4*)(src + (size_t)row * (k8 * 8) + k);
    float4 v0 = s[0], v1 = s[1];
    float f[8] = {v0.x, v0.y, v0.z, v0.w, v1.x, v1.y, v1.z, v1.w};
    uint32_t ph[4], pl[4];
    #pragma unroll
    for (int j = 0; j < 4; j++) {
        float a = f[2*j], b = f[2*j+1];
        __nv_bfloat16 ha = __float2bfloat16(a), hb = __float2bfloat16(b);
        __nv_bfloat162 vh = {ha, hb};
        __nv_bfloat162 vl = {__float2bfloat16(a - __bfloat162float(ha)),
                             __float2bfloat16(b - __bfloat162float(hb))};
        ph[j] = *(uint32_t*)&vh;
        pl[j] = *(uint32_t*)&vl;
    }
    size_t to = tiled_off(row, k, KT);
    *(uint4*)(hi + to) = make_uint4(ph[0], ph[1], ph[2], ph[3]);
    *(uint4*)(lo + to) = make_uint4(pl[0], pl[1], pl[2], pl[3]);
}

// ---------------------------------------------------------------------------
// h += LN(yo)*g + b; fp32 h + tiled hi/lo
// ---------------------------------------------------------------------------
__global__ void ln_res_kernel(const float* __restrict__ gam,
                              const float* __restrict__ bet)
{
    int b = blockIdx.x;
    int t = threadIdx.x;
    __shared__ float sa[8], sbs[8], smu, sinv;
    int d = t * 4;
    float4 v4 = *(const float4*)(g_yo + (size_t)b * DM + d);
    float vv[4] = {v4.x, v4.y, v4.z, v4.w};
    float s = vv[0] + vv[1] + vv[2] + vv[3];
    float s2 = vv[0]*vv[0] + vv[1]*vv[1] + vv[2]*vv[2] + vv[3]*vv[3];
    int lane = t & 31, w = t >> 5;
    #pragma unroll
    for (int o = 16; o; o >>= 1) {
        s  += __shfl_down_sync(0xffffffffu, s,  o);
        s2 += __shfl_down_sync(0xffffffffu, s2, o);
    }
    if (lane == 0) { sa[w] = s; sbs[w] = s2; }
    __syncthreads();
    if (w == 0) {
        s  = (lane < 8) ? sa[lane] : 0.f;
        s2 = (lane < 8) ? sbs[lane] : 0.f;
        #pragma unroll
        for (int o = 4; o; o >>= 1) {
            s  += __shfl_down_sync(0xffffffffu, s,  o);
            s2 += __shfl_down_sync(0xffffffffu, s2, o);
        }
        if (lane == 0) {
            float mu = s / DM;
            float var = s2 / DM - mu * mu;
            smu = mu;
            sinv = rsqrtf(var + 1e-5f);
        }
    }
    __syncthreads();
    float mu = smu, inv = sinv;
    float hv[4];
    #pragma unroll
    for (int j = 0; j < 4; j++) {
        size_t o = (size_t)b * DM + d + j;
        hv[j] = g_h[o] + (vv[j] - mu) * inv * gam[d + j] + bet[d + j];
        g_h[o] = hv[j];
    }
    uint32_t ph[2], pl[2];
    #pragma unroll
    for (int j = 0; j < 2; j++) {
        __nv_bfloat16 ha = __float2bfloat16(hv[2*j]), hb = __float2bfloat16(hv[2*j+1]);
        __nv_bfloat162 vh = {ha, hb};
        __nv_bfloat162 vl = {__float2bfloat16(hv[2*j]   - __bfloat162float(ha)),
                             __float2bfloat16(hv[2*j+1] - __bfloat162float(hb))};
        ph[j] = *(uint32_t*)&vh; pl[j] = *(uint32_t*)&vl;
    }
    size_t to = tiled_off(b, d, DM / 64);
    *(uint2*)(t_h_hi + to) = make_uint2(ph[0], ph[1]);
    *(uint2*)(t_h_lo + to) = make_uint2(pl[0], pl[1]);
}

// ---------------------------------------------------------------------------
// Host launcher
// ---------------------------------------------------------------------------
extern "C" void kernel_launch(void* const* d_in, const int* in_sizes, int n_in,
                              void* d_out, int out_size)
{
    const float* x        = (const float*)d_in[0];
    const float* inp_w    = (const float*)d_in[1];
    const float* inp_b    = (const float*)d_in[2];
    const float* in_proj  = (const float*)d_in[3];
    const float* conv_w   = (const float*)d_in[4];
    const float* conv_b   = (const float*)d_in[5];
    const float* xproj_w  = (const float*)d_in[6];
    const float* dt_w     = (const float*)d_in[7];
    const float* dt_b     = (const float*)d_in[8];
    // d_in[9] = A_log : dead (h0 == 0, single scan step)
    const float* D_param  = (const float*)d_in[10];
    const float* out_w    = (const float*)d_in[11];
    const float* ln_g     = (const float*)d_in[12];
    const float* ln_b     = (const float*)d_in[13];
    const float* outp_w   = (const float*)d_in[14];
    const float* outp_b   = (const float*)d_in[15];
    float* out = (float*)d_out;

    float *p_h, *p_yo, *p_part;
    float2 *p_cvp, *p_dtq;
    cudaGetSymbolAddress((void**)&p_h,    g_h);
    cudaGetSymbolAddress((void**)&p_yo,   g_yo);
    cudaGetSymbolAddress((void**)&p_part, g_part);
    cudaGetSymbolAddress((void**)&p_cvp,  g_cvp);
    cudaGetSymbolAddress((void**)&p_dtq,  g_dtq);

    __nv_bfloat16 *xh, *xl, *hh, *hl, *xch, *xcl, *xdh, *xdl, *yh, *yl;
    cudaGetSymbolAddress((void**)&xh,  t_x_hi);  cudaGetSymbolAddress((void**)&xl,  t_x_lo);
    cudaGetSymbolAddress((void**)&hh,  t_h_hi);  cudaGetSymbolAddress((void**)&hl,  t_h_lo);
    cudaGetSymbolAddress((void**)&xch, t_xc_hi); cudaGetSymbolAddress((void**)&xcl, t_xc_lo);
    cudaGetSymbolAddress((void**)&xdh, t_xd_hi); cudaGetSymbolAddress((void**)&xdl, t_xd_lo);
    cudaGetSymbolAddress((void**)&yh,  t_y_hi);  cudaGetSymbolAddress((void**)&yl,  t_y_lo);

    __nv_bfloat16 *wih, *wil, *wph, *wpl, *wxh, *wxl, *wdh, *wdl, *woh, *wol, *wqh, *wql;
    cudaGetSymbolAddress((void**)&wih, t_wi_hi); cudaGetSymbolAddress((void**)&wil, t_wi_lo);
    cudaGetSymbolAddress((void**)&wph, t_wp_hi); cudaGetSymbolAddress((void**)&wpl, t_wp_lo);
    cudaGetSymbolAddress((void**)&wxh, t_wx_hi); cudaGetSymbolAddress((void**)&wxl, t_wx_lo);
    cudaGetSymbolAddress((void**)&wdh, t_wd_hi); cudaGetSymbolAddress((void**)&wdl, t_wd_lo);
    cudaGetSymbolAddress((void**)&woh, t_wo_hi); cudaGetSymbolAddress((void**)&wol, t_wo_lo);
    cudaGetSymbolAddress((void**)&wqh, t_wq_hi); cudaGetSymbolAddress((void**)&wql, t_wq_lo);

    cudaFuncSetAttribute(gemm_tc<0>, cudaFuncAttributeMaxDynamicSharedMemorySize, GEMM_SMEM);
    cudaFuncSetAttribute(gemm_tc<1>, cudaFuncAttributeMaxDynamicSharedMemorySize, GEMM_SMEM);
    cudaFuncSetAttribute(gemm_tc<2>, cudaFuncAttributeMaxDynamicSharedMemorySize, GEMM_SMEM);

    auto cvt = [](const float* s, __nv_bfloat16* h, __nv_bfloat16* l, int R, int K) {
        int n = R * (K / 8);
        cvt_tiled<<<(n + 255) / 256, 256>>>(s, h, l, R, K / 8, K / 64);
    };
    cvt(x,       xh,  xl,  BATCH, IN_DIM);
    cvt(inp_w,   wih, wil, DM, IN_DIM);
    cvt(in_proj, wph, wpl, NL * 2 * DI, DM);
    for (int l = 0; l < NL; l++)
        cvt(xproj_w + (size_t)l * XD * DI, wxh + (size_t)l * 128 * DI,
            wxl + (size_t)l * 128 * DI, XD, DI);
    cvt(dt_w,    wdh, wdl, NL * DI, DTR);
    cvt(out_w,   woh, wol, NL * DM, DI);
    cvt(outp_w,  wqh, wql, OUT_DIM, DM);
    pack_aux_kernel<<<(NL * DI + 255) / 256, 256>>>(conv_w, conv_b, dt_b, D_param);

    dim3 blk(256);

    // h = x @ inp_w^T + inp_b  (emits tiled hi/lo)
    gemm_tc<0><<<dim3(DM/128, BATCH/128, 1), blk, GEMM_SMEM>>>(
        xh, xl, IN_DIM/64, wih, wil, IN_DIM/64, IN_DIM/64,
        inp_b, p_h, DM, hh, hl, DM/64, nullptr);

    for (int l = 0; l < NL; l++) {
        const __nv_bfloat16* iph = wph + (size_t)l * 2 * DI * DM;
        const __nv_bfloat16* ipl = wpl + (size_t)l * 2 * DI * DM;
        const __nv_bfloat16* xpj = wxh + (size_t)l * 128 * DI;
        const __nv_bfloat16* xpl2= wxl + (size_t)l * 128 * DI;
        const __nv_bfloat16* dth = wdh + (size_t)l * DI * DTR;
        const __nv_bfloat16* dtl = wdl + (size_t)l * DI * DTR;
        const __nv_bfloat16* ohh = woh + (size_t)l * DM * DI;
        const __nv_bfloat16* oll = wol + (size_t)l * DM * DI;
        const float* lg  = ln_g + (size_t)l * DM;
        const float* lb  = ln_b + (size_t)l * DM;

        // xz GEMM with fused conv+silu epilogue
        gemm_tc<1><<<dim3(2*DI/128, BATCH/128, 1), blk, GEMM_SMEM>>>(
            hh, hl, DM/64, iph, ipl, DM/64, DM/64,
            nullptr, nullptr, 2*DI, nullptr, nullptr, 0, p_cvp + (size_t)l * DI);
        // x_dbl partials: split-K x4 (each K=512)
        gemm_tc<0><<<dim3(1, BATCH/128, 4), blk, GEMM_SMEM>>>(
            xch, xcl, DI/64, xpj, xpl2, DI/64, (DI/64)/4,
            nullptr, p_part, 128, nullptr, nullptr, 0, nullptr);
        reduce_xdbl_kernel<<<BATCH, 128>>>();
        // dt GEMM with fused gate epilogue
        gemm_tc<2><<<dim3(DI/128, BATCH/128, 1), blk, GEMM_SMEM>>>(
            xdh, xdl, 2, dth, dtl, 1, 1,
            nullptr, nullptr, DI, nullptr, nullptr, 0, p_dtq + (size_t)l * DI);
        // yo = y @ out_w^T
        gemm_tc<0><<<dim3(DM/128, BATCH/128, 1), blk, GEMM_SMEM>>>(
            yh, yl, DI/64, ohh, oll, DI/64, DI/64,
            nullptr, p_yo, DM, nullptr, nullptr, 0, nullptr);
        ln_res_kernel<<<BATCH, 256>>>(lg, lb);
    }

    // out partials: split-K x4 (each K=256), then reduce + bias
    gemm_tc<0><<<dim3(1, BATCH/128, 4), blk, GEMM_SMEM>>>(
        hh, hl, DM/64, wqh, wql, DM/64, (DM/64)/4,
        nullptr, p_part, 128, nullptr, nullptr, 0, nullptr);
    reduce_out_kernel<<<BATCH, 128>>>(outp_b, out);
    (void)in_sizes; (void)n_in; (void)out_size;
}

// round 12
// speedup vs baseline: 1.1692x; 1.1354x over previous
#include <cuda_runtime.h>
#include <cuda_bf16.h>
#include <cstdint>
#include <math.h>

// Problem constants
#define NL  4
#define DM  1024
#define DI  2048
#define DS  16
#define DC  4
#define DTR 64
#define IN_DIM  256
#define OUT_DIM 128
#define BATCH 4096
#define XD 96          // DTR + 2*DS

// ---------------------------------------------------------------------------
// fp32 scratch
// ---------------------------------------------------------------------------
__device__ float g_h   [BATCH * DM];
__device__ float g_z   [BATCH * DI];        // z half of in_proj output
__device__ float g_xc  [BATCH * DI];
__device__ float g_dtp [BATCH * DI];        // dt pre-softplus
__device__ float g_bc  [BATCH];             // dot(B, C) per row
__device__ float g_yo  [BATCH * DM];
__device__ float g_part[4 * BATCH * 128];   // split-K partials
__device__ float2 g_cvp[NL * DI];           // (conv_b, conv_w[:,DC-1])

// ---------------------------------------------------------------------------
// Tiled bf16 operands. Tile = 128 rows x 64 cols = 16KB, SW128-swizzled.
// ---------------------------------------------------------------------------
__device__ __align__(1024) __nv_bfloat16 t_x_hi [BATCH * IN_DIM], t_x_lo [BATCH * IN_DIM];
__device__ __align__(1024) __nv_bfloat16 t_h_hi [BATCH * DM],     t_h_lo [BATCH * DM];
__device__ __align__(1024) __nv_bfloat16 t_xc_hi[BATCH * DI],     t_xc_lo[BATCH * DI];
__device__ __align__(1024) __nv_bfloat16 t_xd_hi[BATCH * 128],    t_xd_lo[BATCH * 128];
__device__ __align__(1024) __nv_bfloat16 t_y_hi [BATCH * DI],     t_y_lo [BATCH * DI];

__device__ __align__(1024) __nv_bfloat16 t_wi_hi[DM * IN_DIM],       t_wi_lo[DM * IN_DIM];
__device__ __align__(1024) __nv_bfloat16 t_wp_hi[NL * 2 * DI * DM],  t_wp_lo[NL * 2 * DI * DM];
__device__ __align__(1024) __nv_bfloat16 t_wx_hi[NL * 128 * DI],     t_wx_lo[NL * 128 * DI];
__device__ __align__(1024) __nv_bfloat16 t_wd_hi[NL * DI * DTR],     t_wd_lo[NL * DI * DTR];
__device__ __align__(1024) __nv_bfloat16 t_wo_hi[NL * DM * DI],      t_wo_lo[NL * DM * DI];
__device__ __align__(1024) __nv_bfloat16 t_wq_hi[OUT_DIM * DM],      t_wq_lo[OUT_DIM * DM];

// ---------------------------------------------------------------------------
// Tiled addressing
// ---------------------------------------------------------------------------
__device__ __forceinline__ size_t tiled_off(int row, int col, int KT) {
    size_t tile = (size_t)((row >> 7) * KT + (col >> 6));
    uint32_t inner = (uint32_t)((row & 127) * 128)
                   + (((uint32_t)((col & 63) * 2)) ^ ((uint32_t)(row & 7) << 4));
    return tile * 8192 + (inner >> 1);
}

// ---------------------------------------------------------------------------
// PTX helpers
// ---------------------------------------------------------------------------
__device__ __forceinline__ uint32_t smem_u32(const void* p) {
    uint32_t a;
    asm("{ .reg .u64 t; cvta.to.shared.u64 t, %1; cvt.u32.u64 %0, t; }" : "=r"(a) : "l"(p));
    return a;
}
#define MBARRIER_INIT(a, c) \
    asm volatile("mbarrier.init.shared.b64 [%0], %1;" :: "r"((uint32_t)(a)), "r"((uint32_t)(c)) : "memory")
#define MBAR_EXPECT(a, n) \
    asm volatile("mbarrier.arrive.expect_tx.shared.b64 _, [%0], %1;" :: "r"((uint32_t)(a)), "r"((uint32_t)(n)) : "memory")
#define MBAR_ARRIVE(a) \
    asm volatile("mbarrier.arrive.shared.b64 _, [%0];" :: "r"((uint32_t)(a)) : "memory")
#define CP_BULK(sdst, gsrc, nbytes, bar) \
    asm volatile("cp.async.bulk.shared::cta.global.mbarrier::complete_tx::bytes [%0], [%1], %2, [%3];" \
                 :: "r"((uint32_t)(sdst)), "l"(gsrc), "r"((uint32_t)(nbytes)), "r"((uint32_t)(bar)) : "memory")
#define MBARRIER_WAIT_PARITY(mbar_smem_addr, phase_parity) do { \
    uint32_t _mbar = (uint32_t)(mbar_smem_addr); \
    uint32_t _parity = (uint32_t)(phase_parity); \
    uint32_t _done; \
    asm volatile("{\n\t.reg .pred p;\n\t" \
        "mbarrier.try_wait.parity.acquire.cta.shared::cta.b64 p, [%1], %2;\n\t" \
        "selp.b32 %0, 1, 0, p;\n\t}" : "=r"(_done) : "r"(_mbar), "r"(_parity) : "memory"); \
    if (!_done) { \
        asm volatile("{\n\t.reg .pred P1;\n\t" \
            "WAIT_LOOP_%=:\n\t" \
            "mbarrier.try_wait.parity.acquire.cta.shared::cta.b64 P1, [%0], %1, 0x989680;\n\t" \
            "@P1 bra.uni WAIT_DONE_%=;\n\t" \
            "bra.uni WAIT_LOOP_%=;\n\t" \
            "WAIT_DONE_%=:\n\t}" :: "r"(_mbar), "r"(_parity) : "memory"); \
    } \
} while (0)

__device__ __forceinline__ void ldsm4(uint32_t& r0, uint32_t& r1, uint32_t& r2, uint32_t& r3,
                                      uint32_t a) {
    asm volatile("ldmatrix.sync.aligned.m8n8.x4.shared.b16 {%0,%1,%2,%3}, [%4];"
                 : "=r"(r0), "=r"(r1), "=r"(r2), "=r"(r3) : "r"(a));
}
__device__ __forceinline__ void mma_bf16(float* c, const uint32_t* a, const uint32_t* b) {
    asm volatile("mma.sync.aligned.m16n8k16.row.col.f32.bf16.bf16.f32 "
                 "{%0,%1,%2,%3}, {%4,%5,%6,%7}, {%8,%9}, {%0,%1,%2,%3};"
                 : "+f"(c[0]), "+f"(c[1]), "+f"(c[2]), "+f"(c[3])
                 : "r"(a[0]), "r"(a[1]), "r"(a[2]), "r"(a[3]), "r"(b[0]), "r"(b[1]));
}
__device__ __forceinline__ float siluf(float v) { return v / (1.f + expf(-v)); }
__device__ __forceinline__ void split_store(__nv_bfloat16* hi, __nv_bfloat16* lo,
                                            size_t off, float v0, float v1) {
    __nv_bfloat16 h0 = __float2bfloat16(v0), h1 = __float2bfloat16(v1);
    __nv_bfloat162 ph = {h0, h1};
    __nv_bfloat162 pl = {__float2bfloat16(v0 - __bfloat162float(h0)),
                         __float2bfloat16(v1 - __bfloat162float(h1))};
    *(__nv_bfloat162*)(hi + off) = ph;
    *(__nv_bfloat162*)(lo + off) = pl;
}

// ---------------------------------------------------------------------------
// bf16x3 GEMM, bulk-copy 3-stage pipeline, full/empty mbarriers.
// Compile-time MODE:
//   0: plain (+bias, optional fp32 C, optional tiled hi/lo out)
//   1: in_proj epilogue — cols<DI: conv+silu -> g_xc + t_xc ; cols>=DI: z -> g_z
// ---------------------------------------------------------------------------
#define TILE_BYTES 16384
#define STAGE_BYTES (4 * TILE_BYTES)
#define NSTAGE 3
#define GEMM_SMEM (NSTAGE * STAGE_BYTES + 64)

template<int MODE>
__global__ __launch_bounds__(256, 1)
void gemm_tc(const __nv_bfloat16* __restrict__ Ah, const __nv_bfloat16* __restrict__ Al, int KTa,
             const __nv_bfloat16* __restrict__ Wh, const __nv_bfloat16* __restrict__ Wl, int KTb,
             int niter,
             const float* __restrict__ bias,
             float* __restrict__ C, int N,
             __nv_bfloat16* __restrict__ Chi, __nv_bfloat16* __restrict__ Clo, int NT,
             const float2* __restrict__ aux)
{
    extern __shared__ char smem[];
    const uint32_t sbase = smem_u32(smem);
    const uint32_t sfull = sbase + NSTAGE * STAGE_BYTES;
    const uint32_t sempt = sfull + NSTAGE * 8;

    const int tid  = threadIdx.x;
    const int wid  = tid >> 5;
    const int lane = tid & 31;
    const int rbA = blockIdx.y;
    const int rbB = blockIdx.x;
    const int kOff = blockIdx.z * niter;
    if (MODE == 0 && C) C += (size_t)blockIdx.z * BATCH * N;

    if (tid == 0) {
        #pragma unroll
        for (int s = 0; s < NSTAGE; s++) {
            MBARRIER_INIT(sfull + s * 8, 1);
            MBARRIER_INIT(sempt + s * 8, 8);
        }
        asm volatile("fence.proxy.async.shared::cta;" ::: "memory");
    }
    __syncthreads();

    const char* pAh = (const char*)Ah;
    const char* pAl = (const char*)Al;
    const char* pWh = (const char*)Wh;
    const char* pWl = (const char*)Wl;

    auto issue = [&](int kb, int s) {
        uint32_t st = sbase + s * STAGE_BYTES;
        uint32_t bar = sfull + s * 8;
        MBAR_EXPECT(bar, 4 * TILE_BYTES);
        size_t oa = ((size_t)(rbA * KTa + kOff + kb)) << 14;
        size_t ob = ((size_t)(rbB * KTb + kOff + kb)) << 14;
        CP_BULK(st,                  pAh + oa, TILE_BYTES, bar);
        CP_BULK(st + TILE_BYTES,     pAl + oa, TILE_BYTES, bar);
        CP_BULK(st + 2 * TILE_BYTES, pWh + ob, TILE_BYTES, bar);
        CP_BULK(st + 3 * TILE_BYTES, pWl + ob, TILE_BYTES, bar);
    };

    if (tid == 0) {
        #pragma unroll
        for (int s = 0; s < NSTAGE; s++)
            if (s < niter) issue(s, s);
    }

    const int lm = lane >> 3;
    const int lr = lane & 7;
    const int wm = (wid >> 2) * 64;
    const int wn = (wid & 3) * 32;
    const uint32_t xmask = (uint32_t)lr << 4;
    const uint32_t arow = (uint32_t)(wm + (lm & 1) * 8 + lr) * 128;
    const uint32_t aseg = (uint32_t)(lm >> 1) * 16;
    const uint32_t brow = (uint32_t)(wn + (lm >> 1) * 8 + lr) * 128;
    const uint32_t bseg = (uint32_t)(lm & 1) * 16;

    float acc[4][4][4];
    #pragma unroll
    for (int i = 0; i < 4; i++)
        #pragma unroll
        for (int j = 0; j < 4; j++)
            #pragma unroll
            for (int q = 0; q < 4; q++) acc[i][j][q] = 0.f;

    for (int kb = 0; kb < niter; kb++) {
        const int s = kb % NSTAGE;
        const int ph = (kb / NSTAGE) & 1;
        MBARRIER_WAIT_PARITY(sfull + s * 8, ph);
        uint32_t st  = sbase + s * STAGE_BYTES;
        uint32_t sAh = st;
        uint32_t sAl = st + TILE_BYTES;
        uint32_t sBh = st + 2 * TILE_BYTES;
        uint32_t sBl = st + 3 * TILE_BYTES;

        #pragma unroll
        for (int kk = 0; kk < 4; kk++) {
            uint32_t ka  = ((uint32_t)(kk * 32) + aseg) ^ xmask;
            uint32_t kbo = ((uint32_t)(kk * 32) + bseg) ^ xmask;
            uint32_t bh[4][2], bl[4][2];
            #pragma unroll
            for (int p = 0; p < 2; p++) {
                ldsm4(bh[2*p][0], bh[2*p][1], bh[2*p+1][0], bh[2*p+1][1],
                      sBh + brow + p * 2048 + kbo);
                ldsm4(bl[2*p][0], bl[2*p][1], bl[2*p+1][0], bl[2*p+1][1],
                      sBl + brow + p * 2048 + kbo);
            }
            #pragma unroll
            for (int mi = 0; mi < 4; mi++) {
                uint32_t ah[4], al[4];
                ldsm4(ah[0], ah[1], ah[2], ah[3], sAh + arow + mi * 2048 + ka);
                ldsm4(al[0], al[1], al[2], al[3], sAl + arow + mi * 2048 + ka);
                #pragma unroll
                for (int ni = 0; ni < 4; ni++) {
                    mma_bf16(acc[mi][ni], ah, bh[ni]);
                    mma_bf16(acc[mi][ni], ah, bl[ni]);
                    mma_bf16(acc[mi][ni], al, bh[ni]);
                }
            }
        }
        if (lane == 0) MBAR_ARRIVE(sempt + s * 8);
        if (tid == 0 && kb + NSTAGE < niter) {
            MBARRIER_WAIT_PARITY(sempt + s * 8, ph);
            issue(kb + NSTAGE, s);
        }
    }

    // ---- epilogue ----
    const int g = lane >> 2, t4 = lane & 3;
    const int bm = rbA * 128, bn = rbB * 128;
    #pragma unroll
    for (int mi = 0; mi < 4; mi++) {
        #pragma unroll
        for (int ni = 0; ni < 4; ni++) {
            int col = bn + wn + ni * 8 + t4 * 2;
            #pragma unroll
            for (int hrow = 0; hrow < 2; hrow++) {
                int row = bm + wm + mi * 16 + g + hrow * 8;
                float v0 = acc[mi][ni][hrow * 2 + 0];
                float v1 = acc[mi][ni][hrow * 2 + 1];
                if (MODE == 0) {
                    if (bias && col < N) { v0 += bias[col]; v1 += bias[col + 1]; }
                    if (C && col < N)
                        *(float2*)(C + (size_t)row * N + col) = make_float2(v0, v1);
                    if (Chi)
                        split_store(Chi, Clo, tiled_off(row, col, NT), v0, v1);
                } else {
                    if (col < DI) {
                        float2 a0 = aux[col], a1 = aux[col + 1];
                        float x0 = siluf(a0.x + v0 * a0.y);
                        float x1 = siluf(a1.x + v1 * a1.y);
                        *(float2*)(g_xc + (size_t)row * DI + col) = make_float2(x0, x1);
                        split_store(t_xc_hi, t_xc_lo, tiled_off(row, col, DI / 64), x0, x1);
                    } else {
                        *(float2*)(g_z + (size_t)row * DI + (col - DI)) = make_float2(v0, v1);
                    }
                }
            }
        }
    }
}

// ---------------------------------------------------------------------------
// pack (conv_b, conv_w[:,DC-1])
// ---------------------------------------------------------------------------
__global__ void pack_cvp_kernel(const float* __restrict__ cw, const float* __restrict__ cb)
{
    int i = blockIdx.x * 256 + threadIdx.x;
    if (i >= NL * DI) return;
    g_cvp[i] = make_float2(cb[i], cw[i * DC + (DC - 1)]);
}

// ---------------------------------------------------------------------------
// Split-K reduce for xproj: emit tiled hi/lo for dt cols + bc = dot(B,C)
// ---------------------------------------------------------------------------
__global__ void reduce_xdbl_kernel()
{
    int row = blockIdx.x;
    int t = threadIdx.x;   // 128
    __shared__ float sv[128];
    float v = g_part[(size_t)row * 128 + t]
            + g_part[(size_t)BATCH * 128     + (size_t)row * 128 + t]
            + g_part[(size_t)BATCH * 128 * 2 + (size_t)row * 128 + t]
            + g_part[(size_t)BATCH * 128 * 3 + (size_t)row * 128 + t];
    sv[t] = v;
    if (t < DTR) {
        __nv_bfloat16 h = __float2bfloat16(v);
        size_t to = tiled_off(row, t, 2);
        t_xd_hi[to] = h;
        t_xd_lo[to] = __float2bfloat16(v - __bfloat162float(h));
    }
    __syncthreads();
    if (t == 0) {
        float bc = 0.f;
        #pragma unroll
        for (int i = 0; i < DS; i++) bc += sv[DTR + i] * sv[DTR + DS + i];
        g_bc[row] = bc;
    }
}

// ---------------------------------------------------------------------------
// Split-K reduce for final projection
// ---------------------------------------------------------------------------
__global__ void reduce_out_kernel(const float* __restrict__ bias,
                                  float* __restrict__ out)
{
    int row = blockIdx.x;
    int t = threadIdx.x;     // 128 = OUT_DIM
    float v = bias[t]
            + g_part[(size_t)row * 128 + t]
            + g_part[(size_t)BATCH * 128     + (size_t)row * 128 + t]
            + g_part[(size_t)BATCH * 128 * 2 + (size_t)row * 128 + t]
            + g_part[(size_t)BATCH * 128 * 3 + (size_t)row * 128 + t];
    out[(size_t)row * OUT_DIM + t] = v;
}

// ---------------------------------------------------------------------------
// Single fused weight/input conversion: fp32 [R,K] -> tiled bf16 hi/lo,
// all segments in one launch (segment table passed by value).
// ---------------------------------------------------------------------------
#define NSEG 10
struct CvtSegs {
    const float* src[NSEG];
    __nv_bfloat16* hi[NSEG];
    __nv_bfloat16* lo[NSEG];
    int end[NSEG];    // exclusive prefix sum of chunk counts
    int k8[NSEG];
    int KT[NSEG];
};

__global__ void cvt_all_kernel(CvtSegs S, int total)
{
    int idx = blockIdx.x * 256 + threadIdx.x;
    if (idx >= total) return;
    int s = 0;
    #pragma unroll
    for (int i = 0; i < NSEG - 1; i++)
        if (idx >= S.end[i]) s = i + 1;
    int start = (s == 0) ? 0 : S.end[s - 1];
    int local = idx - start;
    int k8 = S.k8[s];
    int row = local / k8;
    int k = (local - row * k8) * 8;
    const float4* sp = (const float4*)(S.src[s] + (size_t)row * (k8 * 8) + k);
    float4 v0 = sp[0], v1 = sp[1];
    float f[8] = {v0.x, v0.y, v0.z, v0.w, v1.x, v1.y, v1.z, v1.w};
    uint32_t ph[4], pl[4];
    #pragma unroll
    for (int j = 0; j < 4; j++) {
        float a = f[2*j], b = f[2*j+1];
        __nv_bfloat16 ha = __float2bfloat16(a), hb = __float2bfloat16(b);
        __nv_bfloat162 vh = {ha, hb};
        __nv_bfloat162 vl = {__float2bfloat16(a - __bfloat162float(ha)),
                             __float2bfloat16(b - __bfloat162float(hb))};
        ph[j] = *(uint32_t*)&vh;
        pl[j] = *(uint32_t*)&vl;
    }
    size_t to = tiled_off(row, k, S.KT[s]);
    *(uint4*)(S.hi[s] + to) = make_uint4(ph[0], ph[1], ph[2], ph[3]);
    *(uint4*)(S.lo[s] + to) = make_uint4(pl[0], pl[1], pl[2], pl[3]);
}

// ---------------------------------------------------------------------------
// y = xc * (softplus(dtp+dtb)*bc + Dp) * silu(z) -> tiled hi/lo (coalesced)
// ---------------------------------------------------------------------------
__global__ void gate_kernel(const float* __restrict__ dtb,
                            const float* __restrict__ Dp)
{
    int b = blockIdx.x;
    int t = threadIdx.x;
    float bc = g_bc[b];
    int e = t * 8;
    const float4* sd = (const float4*)(g_dtp + (size_t)b * DI + e);
    const float4* sx = (const float4*)(g_xc  + (size_t)b * DI + e);
    const float4* sz = (const float4*)(g_z   + (size_t)b * DI + e);
    float4 d0 = sd[0], d1 = sd[1], x0 = sx[0], x1 = sx[1], z0 = sz[0], z1 = sz[1];
    float dv[8] = {d0.x,d0.y,d0.z,d0.w,d1.x,d1.y,d1.z,d1.w};
    float xv[8] = {x0.x,x0.y,x0.z,x0.w,x1.x,x1.y,x1.z,x1.w};
    float zv[8] = {z0.x,z0.y,z0.z,z0.w,z1.x,z1.y,z1.z,z1.w};
    float y[8];
    #pragma unroll
    for (int j = 0; j < 8; j++) {
        float dp = dv[j] + dtb[e + j];
        float dt = (dp > 20.f) ? dp : log1pf(expf(dp));
        y[j] = xv[j] * (dt * bc + Dp[e + j]) * siluf(zv[j]);
    }
    uint32_t ph[4], pl[4];
    #pragma unroll
    for (int j = 0; j < 4; j++) {
        __nv_bfloat16 ha = __float2bfloat16(y[2*j]), hb = __float2bfloat16(y[2*j+1]);
        __nv_bfloat162 vh = {ha, hb};
        __nv_bfloat162 vl = {__float2bfloat16(y[2*j]   - __bfloat162float(ha)),
                             __float2bfloat16(y[2*j+1] - __bfloat162float(hb))};
        ph[j] = *(uint32_t*)&vh; pl[j] = *(uint32_t*)&vl;
    }
    size_t to = tiled_off(b, e, DI / 64);
    *(uint4*)(t_y_hi + to) = make_uint4(ph[0], ph[1], ph[2], ph[3]);
    *(uint4*)(t_y_lo + to) = make_uint4(pl[0], pl[1], pl[2], pl[3]);
}

// ---------------------------------------------------------------------------
// h += LN(yo)*g + b; fp32 h + tiled hi/lo
// ---------------------------------------------------------------------------
__global__ void ln_res_kernel(const float* __restrict__ gam,
                              const float* __restrict__ bet)
{
    int b = blockIdx.x;
    int t = threadIdx.x;
    __shared__ float sa[8], sbs[8], smu, sinv;
    int d = t * 4;
    float4 v4 = *(const float4*)(g_yo + (size_t)b * DM + d);
    float vv[4] = {v4.x, v4.y, v4.z, v4.w};
    float s = vv[0] + vv[1] + vv[2] + vv[3];
    float s2 = vv[0]*vv[0] + vv[1]*vv[1] + vv[2]*vv[2] + vv[3]*vv[3];
    int lane = t & 31, w = t >> 5;
    #pragma unroll
    for (int o = 16; o; o >>= 1) {
        s  += __shfl_down_sync(0xffffffffu, s,  o);
        s2 += __shfl_down_sync(0xffffffffu, s2, o);
    }
    if (lane == 0) { sa[w] = s; sbs[w] = s2; }
    __syncthreads();
    if (w == 0) {
        s  = (lane < 8) ? sa[lane] : 0.f;
        s2 = (lane < 8) ? sbs[lane] : 0.f;
        #pragma unroll
        for (int o = 4; o; o >>= 1) {
            s  += __shfl_down_sync(0xffffffffu, s,  o);
            s2 += __shfl_down_sync(0xffffffffu, s2, o);
        }
        if (lane == 0) {
            float mu = s / DM;
            float var = s2 / DM - mu * mu;
            smu = mu;
            sinv = rsqrtf(var + 1e-5f);
        }
    }
    __syncthreads();
    float mu = smu, inv = sinv;
    float hv[4];
    #pragma unroll
    for (int j = 0; j < 4; j++) {
        size_t o = (size_t)b * DM + d + j;
        hv[j] = g_h[o] + (vv[j] - mu) * inv * gam[d + j] + bet[d + j];
        g_h[o] = hv[j];
    }
    uint32_t ph[2], pl[2];
    #pragma unroll
    for (int j = 0; j < 2; j++) {
        __nv_bfloat16 ha = __float2bfloat16(hv[2*j]), hb = __float2bfloat16(hv[2*j+1]);
        __nv_bfloat162 vh = {ha, hb};
        __nv_bfloat162 vl = {__float2bfloat16(hv[2*j]   - __bfloat162float(ha)),
                             __float2bfloat16(hv[2*j+1] - __bfloat162float(hb))};
        ph[j] = *(uint32_t*)&vh; pl[j] = *(uint32_t*)&vl;
    }
    size_t to = tiled_off(b, d, DM / 64);
    *(uint2*)(t_h_hi + to) = make_uint2(ph[0], ph[1]);
    *(uint2*)(t_h_lo + to) = make_uint2(pl[0], pl[1]);
}

// ---------------------------------------------------------------------------
// Host launcher
// ---------------------------------------------------------------------------
extern "C" void kernel_launch(void* const* d_in, const int* in_sizes, int n_in,
                              void* d_out, int out_size)
{
    const float* x        = (const float*)d_in[0];
    const float* inp_w    = (const float*)d_in[1];
    const float* inp_b    = (const float*)d_in[2];
    const float* in_proj  = (const float*)d_in[3];
    const float* conv_w   = (const float*)d_in[4];
    const float* conv_b   = (const float*)d_in[5];
    const float* xproj_w  = (const float*)d_in[6];
    const float* dt_w     = (const float*)d_in[7];
    const float* dt_b     = (const float*)d_in[8];
    // d_in[9] = A_log : dead (h0 == 0, single scan step)
    const float* D_param  = (const float*)d_in[10];
    const float* out_w    = (const float*)d_in[11];
    const float* ln_g     = (const float*)d_in[12];
    const float* ln_b     = (const float*)d_in[13];
    const float* outp_w   = (const float*)d_in[14];
    const float* outp_b   = (const float*)d_in[15];
    float* out = (float*)d_out;

    float *p_h, *p_dtp, *p_yo, *p_part;
    float2 *p_cvp;
    cudaGetSymbolAddress((void**)&p_h,    g_h);
    cudaGetSymbolAddress((void**)&p_dtp,  g_dtp);
    cudaGetSymbolAddress((void**)&p_yo,   g_yo);
    cudaGetSymbolAddress((void**)&p_part, g_part);
    cudaGetSymbolAddress((void**)&p_cvp,  g_cvp);

    __nv_bfloat16 *xh, *xl, *hh, *hl, *xch, *xcl, *xdh, *xdl, *yh, *yl;
    cudaGetSymbolAddress((void**)&xh,  t_x_hi);  cudaGetSymbolAddress((void**)&xl,  t_x_lo);
    cudaGetSymbolAddress((void**)&hh,  t_h_hi);  cudaGetSymbolAddress((void**)&hl,  t_h_lo);
    cudaGetSymbolAddress((void**)&xch, t_xc_hi); cudaGetSymbolAddress((void**)&xcl, t_xc_lo);
    cudaGetSymbolAddress((void**)&xdh, t_xd_hi); cudaGetSymbolAddress((void**)&xdl, t_xd_lo);
    cudaGetSymbolAddress((void**)&yh,  t_y_hi);  cudaGetSymbolAddress((void**)&yl,  t_y_lo);

    __nv_bfloat16 *wih, *wil, *wph, *wpl, *wxh, *wxl, *wdh, *wdl, *woh, *wol, *wqh, *wql;
    cudaGetSymbolAddress((void**)&wih, t_wi_hi); cudaGetSymbolAddress((void**)&wil, t_wi_lo);
    cudaGetSymbolAddress((void**)&wph, t_wp_hi); cudaGetSymbolAddress((void**)&wpl, t_wp_lo);
    cudaGetSymbolAddress((void**)&wxh, t_wx_hi); cudaGetSymbolAddress((void**)&wxl, t_wx_lo);
    cudaGetSymbolAddress((void**)&wdh, t_wd_hi); cudaGetSymbolAddress((void**)&wdl, t_wd_lo);
    cudaGetSymbolAddress((void**)&woh, t_wo_hi); cudaGetSymbolAddress((void**)&wol, t_wo_lo);
    cudaGetSymbolAddress((void**)&wqh, t_wq_hi); cudaGetSymbolAddress((void**)&wql, t_wq_lo);

    cudaFuncSetAttribute(gemm_tc<0>, cudaFuncAttributeMaxDynamicSharedMemorySize, GEMM_SMEM);
    cudaFuncSetAttribute(gemm_tc<1>, cudaFuncAttributeMaxDynamicSharedMemorySize, GEMM_SMEM);

    // ---- single fused conversion launch ----
    CvtSegs S;
    int pos = 0, si = 0;
    auto add = [&](const float* src, __nv_bfloat16* hi, __nv_bfloat16* lo, int R, int K) {
        S.src[si] = src; S.hi[si] = hi; S.lo[si] = lo;
        S.k8[si] = K / 8; S.KT[si] = K / 64;
        pos += R * (K / 8);
        S.end[si] = pos;
        si++;
    };
    add(x,       xh,  xl,  BATCH, IN_DIM);
    add(inp_w,   wih, wil, DM, IN_DIM);
    add(in_proj, wph, wpl, NL * 2 * DI, DM);
    for (int l = 0; l < NL; l++)
        add(xproj_w + (size_t)l * XD * DI, wxh + (size_t)l * 128 * DI,
            wxl + (size_t)l * 128 * DI, XD, DI);
    add(dt_w,    wdh, wdl, NL * DI, DTR);
    add(out_w,   woh, wol, NL * DM, DI);
    add(outp_w,  wqh, wql, OUT_DIM, DM);
    cvt_all_kernel<<<(pos + 255) / 256, 256>>>(S, pos);
    pack_cvp_kernel<<<(NL * DI + 255) / 256, 256>>>(conv_w, conv_b);

    dim3 blk(256);

    // h = x @ inp_w^T + inp_b  (emits tiled hi/lo)
    gemm_tc<0><<<dim3(DM/128, BATCH/128, 1), blk, GEMM_SMEM>>>(
        xh, xl, IN_DIM/64, wih, wil, IN_DIM/64, IN_DIM/64,
        inp_b, p_h, DM, hh, hl, DM/64, nullptr);

    for (int l = 0; l < NL; l++) {
        const __nv_bfloat16* iph = wph + (size_t)l * 2 * DI * DM;
        const __nv_bfloat16* ipl = wpl + (size_t)l * 2 * DI * DM;
        const __nv_bfloat16* xpj = wxh + (size_t)l * 128 * DI;
        const __nv_bfloat16* xpl2= wxl + (size_t)l * 128 * DI;
        const __nv_bfloat16* dth = wdh + (size_t)l * DI * DTR;
        const __nv_bfloat16* dtl = wdl + (size_t)l * DI * DTR;
        const __nv_bfloat16* ohh = woh + (size_t)l * DM * DI;
        const __nv_bfloat16* oll = wol + (size_t)l * DM * DI;
        const float* dtb = dt_b    + (size_t)l * DI;
        const float* Dp  = D_param + (size_t)l * DI;
        const float* lg  = ln_g + (size_t)l * DM;
        const float* lb  = ln_b + (size_t)l * DM;

        // xz GEMM with fused conv+silu epilogue
        gemm_tc<1><<<dim3(2*DI/128, BATCH/128, 1), blk, GEMM_SMEM>>>(
            hh, hl, DM/64, iph, ipl, DM/64, DM/64,
            nullptr, nullptr, 2*DI, nullptr, nullptr, 0, p_cvp + (size_t)l * DI);
        // x_dbl partials: split-K x4 (each K=512)
        gemm_tc<0><<<dim3(1, BATCH/128, 4), blk, GEMM_SMEM>>>(
            xch, xcl, DI/64, xpj, xpl2, DI/64, (DI/64)/4,
            nullptr, p_part, 128, nullptr, nullptr, 0, nullptr);
        reduce_xdbl_kernel<<<BATCH, 128>>>();
        // dt_pre = x_dbl[:, :64] @ dt_w^T  (plain, fp32 out)
        gemm_tc<0><<<dim3(DI/128, BATCH/128, 1), blk, GEMM_SMEM>>>(
            xdh, xdl, 2, dth, dtl, 1, 1,
            nullptr, p_dtp, DI, nullptr, nullptr, 0, nullptr);
        gate_kernel<<<BATCH, 256>>>(dtb, Dp);
        // yo = y @ out_w^T
        gemm_tc<0><<<dim3(DM/128, BATCH/128, 1), blk, GEMM_SMEM>>>(
            yh, yl, DI/64, ohh, oll, DI/64, DI/64,
            nullptr, p_yo, DM, nullptr, nullptr, 0, nullptr);
        ln_res_kernel<<<BATCH, 256>>>(lg, lb);
    }

    // out partials: split-K x4 (each K=256), then reduce + bias
    gemm_tc<0><<<dim3(1, BATCH/128, 4), blk, GEMM_SMEM>>>(
        hh, hl, DM/64, wqh, wql, DM/64, (DM/64)/4,
        nullptr, p_part, 128, nullptr, nullptr, 0, nullptr);
    reduce_out_kernel<<<BATCH, 128>>>(outp_b, out);
    (void)in_sizes; (void)n_in; (void)out_size;
}